// round 2
// baseline (speedup 1.0000x reference)
#include <cuda_runtime.h>
#include <cstdint>

// Problem constants
#define NROWS 16384   // B*X*Y*Z
#define DD    64
#define KCODES 8192
#define SS    4096    // X*Y*Z
#define BB    4
#define KSPLIT 4
#define TK    32      // codebook tile (codes per smem tile)
#define OUT_TENSOR_ELEMS (NROWS*DD)   // 1048576

// Scratch (device globals: allocation-free rule)
__device__ float g_latT[NROWS * DD];          // 4 MB, row-major [n][d]
__device__ float g_cbn[KCODES];               // codebook row norms
__device__ float g_pval[KSPLIT * NROWS];
__device__ int   g_pidx[KSPLIT * NROWS];
__device__ int   g_idx[NROWS];
__device__ float g_losspart[4096];

// Packed f32x2 ops (Blackwell): 2 fp32 FMAs per instruction
#define FMA2(d, a, b, c) \
    asm("fma.rn.f32x2 %0, %1, %2, %3;" : "=l"(d) : "l"(a), "l"(b), "l"(c))
#define ADD2(d, a, b) \
    asm("add.rn.f32x2 %0, %1, %2;" : "=l"(d) : "l"(a), "l"(b))
#define UNPACK2(lo, hi, p) \
    asm("mov.b64 {%0, %1}, %2;" : "=r"(lo), "=r"(hi) : "l"(p))

// ---------------------------------------------------------------------------
// K0: transpose latents [B][D][S] -> latT[(b*S+s)][d]
// ---------------------------------------------------------------------------
__global__ void k_transpose(const float* __restrict__ lat) {
    __shared__ float t[32][33];
    int b = blockIdx.z, d0 = blockIdx.y * 32, s0 = blockIdx.x * 32;
    int tx = threadIdx.x, ty = threadIdx.y;
#pragma unroll
    for (int j = 0; j < 32; j += 8)
        t[ty + j][tx] = lat[((b * DD) + (d0 + ty + j)) * SS + s0 + tx];
    __syncthreads();
#pragma unroll
    for (int j = 0; j < 32; j += 8)
        g_latT[(b * SS + s0 + ty + j) * DD + d0 + tx] = t[tx][ty + j];
}

// ---------------------------------------------------------------------------
// K0b: codebook row norms
// ---------------------------------------------------------------------------
__global__ void k_cbn(const float* __restrict__ cb) {
    int k = blockIdx.x * 256 + threadIdx.x;
    const float4* r = (const float4*)(cb + (size_t)k * DD);
    float a0 = 0.f, a1 = 0.f, a2 = 0.f, a3 = 0.f;
#pragma unroll
    for (int i = 0; i < 16; i++) {
        float4 v = r[i];
        a0 = fmaf(v.x, v.x, a0);
        a1 = fmaf(v.y, v.y, a1);
        a2 = fmaf(v.z, v.z, a2);
        a3 = fmaf(v.w, v.w, a3);
    }
    g_cbn[k] = (a0 + a1) + (a2 + a3);
}

// ---------------------------------------------------------------------------
// K1: per-row argmin over a K-split.
// One thread = one latent row (held in 32 packed f32x2 regs).
// Codebook streamed via smem tiles; all threads read same code -> LDS broadcast.
// Grid (64 rowblocks, KSPLIT), 256 thr -> 256 blocks = 1 wave @ 2 blocks/SM.
// ---------------------------------------------------------------------------
__global__ __launch_bounds__(256, 2) void k_argmin(const float* __restrict__ cb) {
    __shared__ float4 cbs[TK * 16];   // TK codes x 64 floats
    __shared__ float  cbns[TK];
    int tid = threadIdx.x;
    int n = blockIdx.x * 256 + tid;
    int k0 = blockIdx.y * (KCODES / KSPLIT);

    // Load this row as 32 packed f32x2 values
    unsigned long long la[32];
    {
        const ulonglong2* lp = (const ulonglong2*)(g_latT + (size_t)n * DD);
#pragma unroll
        for (int i = 0; i < 16; i++) {
            ulonglong2 v = lp[i];
            la[2 * i] = v.x;
            la[2 * i + 1] = v.y;
        }
    }

    // rn = ||x||^2  (packed)
    float rn;
    {
        unsigned long long r0 = 0ull, r1 = 0ull, r2 = 0ull, r3 = 0ull;
#pragma unroll
        for (int i = 0; i < 32; i += 4) {
            FMA2(r0, la[i],     la[i],     r0);
            FMA2(r1, la[i + 1], la[i + 1], r1);
            FMA2(r2, la[i + 2], la[i + 2], r2);
            FMA2(r3, la[i + 3], la[i + 3], r3);
        }
        unsigned long long s0, s1, s;
        ADD2(s0, r0, r1); ADD2(s1, r2, r3); ADD2(s, s0, s1);
        unsigned lo, hi; UNPACK2(lo, hi, s);
        rn = __uint_as_float(lo) + __uint_as_float(hi);
    }

    float best = 3.4e38f;
    int   bidx = 0;

    for (int t = 0; t < KCODES / KSPLIT; t += TK) {
        __syncthreads();
        const float4* gp = (const float4*)(cb + (size_t)(k0 + t) * DD);
        cbs[tid] = gp[tid];
        cbs[tid + 256] = gp[tid + 256];
        if (tid < TK) cbns[tid] = g_cbn[k0 + t + tid];
        __syncthreads();

#pragma unroll 4
        for (int kk = 0; kk < TK; kk++) {
            const ulonglong2* crow = (const ulonglong2*)(cbs + kk * 16);
            unsigned long long a0 = 0ull, a1 = 0ull, a2 = 0ull, a3 = 0ull;
#pragma unroll
            for (int i = 0; i < 16; i += 2) {
                ulonglong2 c0 = crow[i];
                ulonglong2 c1 = crow[i + 1];
                FMA2(a0, la[2 * i],     c0.x, a0);
                FMA2(a1, la[2 * i + 1], c0.y, a1);
                FMA2(a2, la[2 * i + 2], c1.x, a2);
                FMA2(a3, la[2 * i + 3], c1.y, a3);
            }
            unsigned long long s0, s1, s;
            ADD2(s0, a0, a1); ADD2(s1, a2, a3); ADD2(s, s0, s1);
            unsigned lo, hi; UNPACK2(lo, hi, s);
            float dot = __uint_as_float(lo) + __uint_as_float(hi);
            // Match reference rounding: dist = (rn + cn) - 2*dot, single rounding
            float dist = fmaf(-2.f, dot, rn + cbns[kk]);
            if (dist < best) { best = dist; bidx = k0 + t + kk; }
        }
    }
    g_pval[blockIdx.y * NROWS + n] = best;
    g_pidx[blockIdx.y * NROWS + n] = bidx;
}

// ---------------------------------------------------------------------------
// K2: combine split partials (ascending split order => first-index tiebreak)
// ---------------------------------------------------------------------------
__global__ void k_combine() {
    int n = blockIdx.x * 256 + threadIdx.x;
    float best = g_pval[n];
    int   bi = g_pidx[n];
#pragma unroll
    for (int sp = 1; sp < KSPLIT; sp++) {
        float v = g_pval[sp * NROWS + n];
        int   ix = g_pidx[sp * NROWS + n];
        if (v < best) { best = v; bi = ix; }
    }
    g_idx[n] = bi;
}

// ---------------------------------------------------------------------------
// K3: write output in native [B,D,S] layout (fully coalesced stores),
// gather codebook rows, deterministic block-level loss partials.
// ---------------------------------------------------------------------------
__global__ void k_outloss(const float* __restrict__ lat,
                          const float* __restrict__ cb,
                          float* __restrict__ out) {
    int e = blockIdx.x * 256 + threadIdx.x;     // 4096 blocks cover 1M elems
    int s = e & (SS - 1);
    int bd = e >> 12;
    int d = bd & (DD - 1);
    int b = bd >> 6;
    int n = b * SS + s;
    int idx = g_idx[n];
    float q = cb[(size_t)idx * DD + d];
    float l = lat[e];
    out[e] = q;
    float df = q - l;
    float v = df * df;
#pragma unroll
    for (int o = 16; o > 0; o >>= 1) v += __shfl_down_sync(0xffffffffu, v, o);
    __shared__ float red[8];
    int w = threadIdx.x >> 5, ln = threadIdx.x & 31;
    if (ln == 0) red[w] = v;
    __syncthreads();
    if (threadIdx.x < 32) {
        float x = (threadIdx.x < 8) ? red[threadIdx.x] : 0.f;
#pragma unroll
        for (int o = 4; o > 0; o >>= 1) x += __shfl_down_sync(0xffffffffu, x, o);
        if (threadIdx.x == 0) g_losspart[blockIdx.x] = x;
    }
}

// ---------------------------------------------------------------------------
// K4: final fixed-order reduce -> vq_loss = mse * (1 + w), at out[out_size-1]
// ---------------------------------------------------------------------------
__global__ void k_final(const float* __restrict__ vqw,
                        float* __restrict__ out, int out_size) {
    __shared__ float sm[256];
    int tid = threadIdx.x;
    float a = 0.f;
#pragma unroll
    for (int i = 0; i < 16; i++) a += g_losspart[tid * 16 + i];
    sm[tid] = a;
    __syncthreads();
    for (int o = 128; o > 0; o >>= 1) {
        if (tid < o) sm[tid] += sm[tid + o];
        __syncthreads();
    }
    if (tid == 0 && out_size > OUT_TENSOR_ELEMS) {
        float w = vqw[0];
        out[out_size - 1] = sm[0] * (1.f + w) * (1.f / (float)OUT_TENSOR_ELEMS);
    }
}

// ---------------------------------------------------------------------------
extern "C" void kernel_launch(void* const* d_in, const int* in_sizes, int n_in,
                              void* d_out, int out_size) {
    const float* lat = (const float*)d_in[0];   // latents [4,64,16,16,16] f32
    const float* vqw = (const float*)d_in[1];   // vq_weight scalar f32
    const float* cb  = (const float*)d_in[2];   // codebook [8192,64] f32
    float* out = (float*)d_out;

    k_transpose<<<dim3(SS / 32, DD / 32, BB), dim3(32, 8)>>>(lat);
    k_cbn<<<KCODES / 256, 256>>>(cb);
    k_argmin<<<dim3(NROWS / 256, KSPLIT), 256>>>(cb);
    k_combine<<<NROWS / 256, 256>>>();
    k_outloss<<<OUT_TENSOR_ELEMS / 256, 256>>>(lat, cb, out);
    k_final<<<1, 256>>>(vqw, out, out_size);
}

// round 5
// speedup vs baseline: 1.9049x; 1.9049x over previous
#include <cuda_runtime.h>
#include <cuda_bf16.h>
#include <cstdint>

// ===========================================================================
// Problem constants
// ===========================================================================
#define NROWS 16384          // B*X*Y*Z latent rows
#define DD    64
#define KCODES 8192
#define SS    4096           // X*Y*Z
#define BB    4
#define OUT_TENSOR_ELEMS (NROWS*DD)

#define MTILE 128            // rows per CTA
#define NT    128            // codes per iteration tile
#define NITER (KCODES/NT)    // 64
#define A_BYTES 65536        // 128 rows x 64 k x 2 terms x 4B (fragment order)
#define B_BYTES 65536        // 128 codes x 64 k x 2 terms x 4B (fragment order)

// dynamic smem: A 64K | B0 64K | B1 64K | CN0 512 | CN1 512
#define SM_A   0
#define SM_B0  65536
#define SM_B1  131072
#define SM_CN0 196608
#define SM_CN1 197120
#define DSMEM_BYTES 197632

// ===========================================================================
// Device scratch (allocation-free rule)
// ===========================================================================
__device__ float g_latT[NROWS * DD];           // [n][d]
__device__ float g_rn[NROWS];
__device__ float g_cbn[KCODES];
__device__ float g_latfrag[(NROWS / MTILE) * (A_BYTES / 4)];  // 8 MB
__device__ float g_cbfrag[NITER * (B_BYTES / 4)];             // 4 MB
__device__ int   g_idx[NROWS];
__device__ float g_losspart[4096];

// ===========================================================================
// Small asm helpers
// ===========================================================================
#define FMA2(d, a, b, c) \
    asm("fma.rn.f32x2 %0, %1, %2, %3;" : "=l"(d) : "l"(a), "l"(b), "l"(c))
#define ADD2(d, a, b) \
    asm("add.rn.f32x2 %0, %1, %2;" : "=l"(d) : "l"(a), "l"(b))
#define UNPACK2(lo, hi, p) \
    asm("mov.b64 {%0, %1}, %2;" : "=r"(lo), "=r"(hi) : "l"(p))

__device__ __forceinline__ uint32_t f2tf32(float x) {
    uint32_t r;
    asm("cvt.rna.tf32.f32 %0, %1;" : "=r"(r) : "f"(x));
    return r;
}
__device__ __forceinline__ uint32_t smem_u32(const void* p) {
    uint32_t a;
    asm("{ .reg .u64 t; cvta.to.shared.u64 t, %1; cvt.u32.u64 %0, t; }"
        : "=r"(a) : "l"(p));
    return a;
}
__device__ __forceinline__ void cp16(uint32_t dst, const void* src) {
    asm volatile("cp.async.cg.shared.global [%0], [%1], 16;"
                 :: "r"(dst), "l"(src) : "memory");
}
__device__ __forceinline__ void cp4(uint32_t dst, const void* src) {
    asm volatile("cp.async.ca.shared.global [%0], [%1], 4;"
                 :: "r"(dst), "l"(src) : "memory");
}
#define CP_COMMIT() asm volatile("cp.async.commit_group;" ::: "memory")
#define CP_WAIT1()  asm volatile("cp.async.wait_group 1;" ::: "memory")

__device__ __forceinline__ void mma_tf32(float* c, const uint32_t* a,
                                         const uint32_t* b) {
    asm volatile(
        "mma.sync.aligned.m16n8k8.row.col.f32.tf32.tf32.f32 "
        "{%0,%1,%2,%3}, {%4,%5,%6,%7}, {%8,%9}, {%0,%1,%2,%3};"
        : "+f"(c[0]), "+f"(c[1]), "+f"(c[2]), "+f"(c[3])
        : "r"(a[0]), "r"(a[1]), "r"(a[2]), "r"(a[3]), "r"(b[0]), "r"(b[1]));
}

// ===========================================================================
// K0: transpose latents [B][D][S] -> g_latT[(b*S+s)][d]   (R1-identical)
// ===========================================================================
__global__ void k_transpose(const float* __restrict__ lat) {
    __shared__ float t[32][33];
    int b = blockIdx.z, d0 = blockIdx.y * 32, s0 = blockIdx.x * 32;
    int tx = threadIdx.x, ty = threadIdx.y;
#pragma unroll
    for (int j = 0; j < 32; j += 8)
        t[ty + j][tx] = lat[((b * DD) + (d0 + ty + j)) * SS + s0 + tx];
    __syncthreads();
#pragma unroll
    for (int j = 0; j < 32; j += 8)
        g_latT[(b * SS + s0 + ty + j) * DD + d0 + tx] = t[tx][ty + j];
}

// ===========================================================================
// K0b: codebook norms (R1-identical)
// ===========================================================================
__global__ void k_cbn(const float* __restrict__ cb) {
    int k = blockIdx.x * 256 + threadIdx.x;
    const float4* r = (const float4*)(cb + (size_t)k * DD);
    float a0 = 0.f, a1 = 0.f, a2 = 0.f, a3 = 0.f;
#pragma unroll
    for (int i = 0; i < 16; i++) {
        float4 v = r[i];
        a0 = fmaf(v.x, v.x, a0);
        a1 = fmaf(v.y, v.y, a1);
        a2 = fmaf(v.z, v.z, a2);
        a3 = fmaf(v.w, v.w, a3);
    }
    g_cbn[k] = (a0 + a1) + (a2 + a3);
}

// ===========================================================================
// K0c: row norms (bit-identical to R1's in-kernel order)
// ===========================================================================
__global__ void k_rn() {
    int n = blockIdx.x * 256 + threadIdx.x;
    unsigned long long la[32];
    const ulonglong2* lp = (const ulonglong2*)(g_latT + (size_t)n * DD);
#pragma unroll
    for (int i = 0; i < 16; i++) {
        ulonglong2 v = lp[i];
        la[2 * i] = v.x;
        la[2 * i + 1] = v.y;
    }
    unsigned long long r0 = 0ull, r1 = 0ull, r2 = 0ull, r3 = 0ull;
#pragma unroll
    for (int i = 0; i < 32; i += 4) {
        FMA2(r0, la[i],     la[i],     r0);
        FMA2(r1, la[i + 1], la[i + 1], r1);
        FMA2(r2, la[i + 2], la[i + 2], r2);
        FMA2(r3, la[i + 3], la[i + 3], r3);
    }
    unsigned long long s0, s1, s;
    ADD2(s0, r0, r1); ADD2(s1, r2, r3); ADD2(s, s0, s1);
    unsigned lo, hi; UNPACK2(lo, hi, s);
    g_rn[n] = __uint_as_float(lo) + __uint_as_float(hi);
}

// ===========================================================================
// K0d: build A fragments. float4 per thread.
// Layout blocks (wm4, s8, term2, i2): 32 lanes x float4 (a0,a1,a2,a3).
// ===========================================================================
__global__ void k_afrag() {
    int gid = blockIdx.x * 256 + threadIdx.x;     // 524288 float4s
    int cta = gid >> 12;
    int rem = gid & 4095;
    int wm = rem >> 10;
    int s = (rem >> 7) & 7;
    int t = (rem >> 6) & 1;
    int i = (rem >> 5) & 1;
    int lane = rem & 31;
    int r0 = cta * MTILE + wm * 32 + i * 16 + (lane >> 2);
    int k0 = s * 8 + (lane & 3);
    float4 o;
    float* po = &o.x;
#pragma unroll
    for (int q = 0; q < 4; q++) {
        int dr = (q & 1) * 8;
        int dc = (q >> 1) * 4;
        float x = g_latT[(size_t)(r0 + dr) * DD + k0 + dc];
        uint32_t t1 = f2tf32(x);
        if (t == 0) po[q] = __uint_as_float(t1);
        else        po[q] = __uint_as_float(f2tf32(x - __uint_as_float(t1)));
    }
    ((float4*)g_latfrag)[gid] = o;
}

// ===========================================================================
// K0e: build B fragments. Layout blocks (wn2, s8, term2, p4):
// 32 lanes x float4 = (tile2p.b0, tile2p.b1, tile2p+1.b0, tile2p+1.b1)
// ===========================================================================
__global__ void k_bfrag(const float* __restrict__ cb) {
    int gid = blockIdx.x * 256 + threadIdx.x;     // 262144 float4s
    int tile = gid >> 12;
    int rem = gid & 4095;
    int wn = rem >> 11;
    int s = (rem >> 8) & 7;
    int t = (rem >> 7) & 1;
    int p = (rem >> 5) & 3;
    int lane = rem & 31;
    int g = lane >> 2;
    int k0 = s * 8 + (lane & 3);
    float4 o;
    float* po = &o.x;
#pragma unroll
    for (int c = 0; c < 4; c++) {
        int j = 2 * p + (c >> 1);
        int dk = (c & 1) * 4;
        int code = tile * NT + wn * 64 + j * 8 + g;
        float x = cb[(size_t)code * DD + k0 + dk];
        uint32_t t1 = f2tf32(x);
        if (t == 0) po[c] = __uint_as_float(t1);
        else        po[c] = __uint_as_float(f2tf32(x - __uint_as_float(t1)));
    }
    ((float4*)g_cbfrag)[gid] = o;
}

// ===========================================================================
// K1: tf32 mma.sync GEMM + fused argmin. 128 CTAs x 256 threads.
// ===========================================================================
__global__ void __launch_bounds__(256, 1) k_gemm_argmin() {
    extern __shared__ char sm[];
    uint32_t sbase = smem_u32(sm);
    int tid = threadIdx.x;
    int lane = tid & 31;
    int wid = tid >> 5;
    int wm = wid >> 1;               // 0..3 : rows wm*32..+32
    int wn = wid & 1;                // 0..1 : cols wn*64..+64
    int cta = blockIdx.x;

    // ---- prologue prefetch: A (group0), B0+CN0 (group1), B1+CN1 (group2) ----
    {
        const char* asrc = (const char*)g_latfrag + (size_t)cta * A_BYTES;
#pragma unroll
        for (int c = 0; c < 16; c++)
            cp16(sbase + SM_A + (c * 256 + tid) * 16, asrc + (c * 256 + tid) * 16);
        CP_COMMIT();
        const char* bsrc = (const char*)g_cbfrag;
#pragma unroll
        for (int c = 0; c < 16; c++)
            cp16(sbase + SM_B0 + (c * 256 + tid) * 16, bsrc + (c * 256 + tid) * 16);
        if (tid < 128) cp4(sbase + SM_CN0 + tid * 4, g_cbn + tid);
        CP_COMMIT();
#pragma unroll
        for (int c = 0; c < 16; c++)
            cp16(sbase + SM_B1 + (c * 256 + tid) * 16,
                 bsrc + B_BYTES + (c * 256 + tid) * 16);
        if (tid < 128) cp4(sbase + SM_CN1 + tid * 4, g_cbn + 128 + tid);
        CP_COMMIT();
    }

    // per-thread rows: (i,h) -> cta*128 + wm*32 + i*16 + (lane>>2) + h*8
    float rn[4];
#pragma unroll
    for (int i = 0; i < 2; i++)
#pragma unroll
        for (int h = 0; h < 2; h++)
            rn[i * 2 + h] =
                g_rn[cta * MTILE + wm * 32 + i * 16 + (lane >> 2) + h * 8];

    float bestv[4] = {3.4e38f, 3.4e38f, 3.4e38f, 3.4e38f};
    int   besti[4] = {0, 0, 0, 0};

    // FIXED strides: per-wm A block = 32*512B = 16384; per-wn B block = 64*512B = 32768
    uint32_t a_base = sbase + SM_A + (uint32_t)wm * 16384 + lane * 16;
    uint32_t cn_off = (uint32_t)(wn * 64 + (lane & 3) * 2) * 4;

    for (int t = 0; t < NITER; t++) {
        CP_WAIT1();
        __syncthreads();
        uint32_t b_base = sbase + ((t & 1) ? SM_B1 : SM_B0)
                          + (uint32_t)wn * 32768 + lane * 16;
        uint32_t cn_base = sbase + ((t & 1) ? SM_CN1 : SM_CN0) + cn_off;

        float acc[2][8][4];
#pragma unroll
        for (int i = 0; i < 2; i++)
#pragma unroll
            for (int j = 0; j < 8; j++)
#pragma unroll
                for (int v = 0; v < 4; v++) acc[i][j][v] = 0.f;

        // passes (ta,tb): (0,0), (1,0), (0,1)
#pragma unroll
        for (int pass = 0; pass < 3; pass++) {
            int ta = (pass == 1);
            int tb = (pass == 2);
#pragma unroll
            for (int s = 0; s < 8; s++) {
                uint32_t af[2][4];
#pragma unroll
                for (int i = 0; i < 2; i++) {
                    float4 v;
                    asm volatile("ld.shared.v4.b32 {%0,%1,%2,%3}, [%4];"
                        : "=f"(v.x), "=f"(v.y), "=f"(v.z), "=f"(v.w)
                        : "r"(a_base + ((s * 2 + ta) * 2 + i) * 512u));
                    af[i][0] = __float_as_uint(v.x);
                    af[i][1] = __float_as_uint(v.y);
                    af[i][2] = __float_as_uint(v.z);
                    af[i][3] = __float_as_uint(v.w);
                }
#pragma unroll
                for (int p = 0; p < 4; p++) {
                    float4 v;
                    asm volatile("ld.shared.v4.b32 {%0,%1,%2,%3}, [%4];"
                        : "=f"(v.x), "=f"(v.y), "=f"(v.z), "=f"(v.w)
                        : "r"(b_base + ((s * 2 + tb) * 4 + p) * 512u));
                    uint32_t b0[2] = {__float_as_uint(v.x), __float_as_uint(v.y)};
                    uint32_t b1[2] = {__float_as_uint(v.z), __float_as_uint(v.w)};
#pragma unroll
                    for (int i = 0; i < 2; i++) {
                        mma_tf32(acc[i][2 * p], af[i], b0);
                        mma_tf32(acc[i][2 * p + 1], af[i], b1);
                    }
                }
            }
        }

        // fused argmin epilogue (ascending code index, strict <)
        int kb = t * NT + wn * 64 + 2 * (lane & 3);
#pragma unroll
        for (int j = 0; j < 8; j++) {
            float2 cn2;
            asm volatile("ld.shared.v2.b32 {%0,%1}, [%2];"
                : "=f"(cn2.x), "=f"(cn2.y) : "r"(cn_base + j * 32u));
#pragma unroll
            for (int i = 0; i < 2; i++) {
#pragma unroll
                for (int v = 0; v < 4; v++) {
                    float cn = (v & 1) ? cn2.y : cn2.x;
                    int slot = i * 2 + (v >> 1);
                    float dist = fmaf(-2.f, acc[i][j][v], rn[slot] + cn);
                    int idx = kb + j * 8 + (v & 1);
                    if (dist < bestv[slot]) { bestv[slot] = dist; besti[slot] = idx; }
                }
            }
        }
        __syncthreads();

        // prefetch tile t+2 into the buffer just consumed
        if (t + 2 < NITER) {
            const char* bsrc = (const char*)g_cbfrag + (size_t)(t + 2) * B_BYTES;
            uint32_t dst = sbase + ((t & 1) ? SM_B1 : SM_B0);
#pragma unroll
            for (int c = 0; c < 16; c++)
                cp16(dst + (c * 256 + tid) * 16, bsrc + (c * 256 + tid) * 16);
            if (tid < 128)
                cp4(sbase + ((t & 1) ? SM_CN1 : SM_CN0) + tid * 4,
                    g_cbn + (t + 2) * NT + tid);
        }
        CP_COMMIT();   // unconditional: keeps wait_group(1) accounting correct
    }

    // ---- final cross-thread argmin via u64 keys (dist>0 so bits ordered) ----
    __syncthreads();
    unsigned long long* red = (unsigned long long*)sm;   // reuse A region, 8KB
    int slotcol = wn * 4 + (lane & 3);
#pragma unroll
    for (int i = 0; i < 2; i++)
#pragma unroll
        for (int h = 0; h < 2; h++) {
            int row = wm * 32 + i * 16 + (lane >> 2) + h * 8;
            unsigned long long key =
                ((unsigned long long)__float_as_uint(bestv[i * 2 + h]) << 32)
                | (unsigned)besti[i * 2 + h];
            red[row * 8 + slotcol] = key;
        }
    __syncthreads();
    if (tid < 128) {
        unsigned long long k = red[tid * 8];
#pragma unroll
        for (int c = 1; c < 8; c++) {
            unsigned long long v = red[tid * 8 + c];
            if (v < k) k = v;
        }
        g_idx[cta * MTILE + tid] = (int)(unsigned)k;
    }
}

// ===========================================================================
// K3: output gather (native layout, coalesced) + block loss partials (R1)
// ===========================================================================
__global__ void k_outloss(const float* __restrict__ lat,
                          const float* __restrict__ cb,
                          float* __restrict__ out) {
    int e = blockIdx.x * 256 + threadIdx.x;
    int s = e & (SS - 1);
    int bd = e >> 12;
    int d = bd & (DD - 1);
    int b = bd >> 6;
    int n = b * SS + s;
    int idx = g_idx[n];
    float q = cb[(size_t)idx * DD + d];
    float l = lat[e];
    out[e] = q;
    float df = q - l;
    float v = df * df;
#pragma unroll
    for (int o = 16; o > 0; o >>= 1) v += __shfl_down_sync(0xffffffffu, v, o);
    __shared__ float red[8];
    int w = threadIdx.x >> 5, ln = threadIdx.x & 31;
    if (ln == 0) red[w] = v;
    __syncthreads();
    if (threadIdx.x < 32) {
        float x = (threadIdx.x < 8) ? red[threadIdx.x] : 0.f;
#pragma unroll
        for (int o = 4; o > 0; o >>= 1) x += __shfl_down_sync(0xffffffffu, x, o);
        if (threadIdx.x == 0) g_losspart[blockIdx.x] = x;
    }
}

// ===========================================================================
// K4: final fixed-order reduce (R1)
// ===========================================================================
__global__ void k_final(const float* __restrict__ vqw,
                        float* __restrict__ out, int out_size) {
    __shared__ float sm2[256];
    int tid = threadIdx.x;
    float a = 0.f;
#pragma unroll
    for (int i = 0; i < 16; i++) a += g_losspart[tid * 16 + i];
    sm2[tid] = a;
    __syncthreads();
    for (int o = 128; o > 0; o >>= 1) {
        if (tid < o) sm2[tid] += sm2[tid + o];
        __syncthreads();
    }
    if (tid == 0 && out_size > OUT_TENSOR_ELEMS) {
        float w = vqw[0];
        out[out_size - 1] = sm2[0] * (1.f + w) * (1.f / (float)OUT_TENSOR_ELEMS);
    }
}

// ===========================================================================
extern "C" void kernel_launch(void* const* d_in, const int* in_sizes, int n_in,
                              void* d_out, int out_size) {
    const float* lat = (const float*)d_in[0];
    const float* vqw = (const float*)d_in[1];
    const float* cb  = (const float*)d_in[2];
    float* out = (float*)d_out;

    static int s_attr = 0;
    if (!s_attr) {
        cudaFuncSetAttribute(k_gemm_argmin,
                             cudaFuncAttributeMaxDynamicSharedMemorySize,
                             DSMEM_BYTES);
        s_attr = 1;
    }

    k_transpose<<<dim3(SS / 32, DD / 32, BB), dim3(32, 8)>>>(lat);
    k_cbn<<<KCODES / 256, 256>>>(cb);
    k_rn<<<NROWS / 256, 256>>>();
    k_afrag<<<2048, 256>>>();
    k_bfrag<<<1024, 256>>>(cb);
    k_gemm_argmin<<<NROWS / MTILE, 256, DSMEM_BYTES>>>();
    k_outloss<<<OUT_TENSOR_ELEMS / 256, 256>>>(lat, cb, out);
    k_final<<<1, 256>>>(vqw, out, out_size);
}

// round 6
// speedup vs baseline: 3.1403x; 1.6485x over previous
#include <cuda_runtime.h>
#include <cuda_fp16.h>
#include <cstdint>

// ===========================================================================
// Problem constants
// ===========================================================================
#define NROWS 16384          // B*X*Y*Z latent rows
#define DD    64
#define KCODES 8192
#define SS    4096           // X*Y*Z
#define BB    4
#define OUT_TENSOR_ELEMS (NROWS*DD)

#define MTILE 128            // rows per CTA
#define NT    128            // codes per iteration tile
#define NITER (KCODES/NT)    // 64
#define A_BYTES 32768        // 128 rows x 64 k x 2 terms x 2B (fp16 fragment order)
#define B_BYTES 32768        // 128 codes x 64 k x 2 terms x 2B

// B pre-scaled by 2^13 (exact). Epilogue rescale: -2*dot = -acc * 2^-12.
#define DIST_SCALE (-0.000244140625f)   /* -2^-12 */

// dynamic smem: A 32K | B0 32K | B1 32K | CN0 512 | CN1 512
#define SM_A   0
#define SM_B0  32768
#define SM_B1  65536
#define SM_CN0 98304
#define SM_CN1 98816
#define DSMEM_BYTES 99328

// ===========================================================================
// Device scratch (allocation-free rule)
// ===========================================================================
__device__ float g_latT[NROWS * DD];           // [n][d]
__device__ float g_rn[NROWS];
__device__ float g_cbn[KCODES];
__device__ uint4 g_latfrag[(NROWS / MTILE) * (A_BYTES / 16)];  // 4 MB
__device__ uint4 g_cbfrag[NITER * (B_BYTES / 16)];             // 2 MB
__device__ int   g_idx[NROWS];
__device__ float g_losspart[4096];

// ===========================================================================
// Small asm helpers
// ===========================================================================
#define FMA2(d, a, b, c) \
    asm("fma.rn.f32x2 %0, %1, %2, %3;" : "=l"(d) : "l"(a), "l"(b), "l"(c))
#define ADD2(d, a, b) \
    asm("add.rn.f32x2 %0, %1, %2;" : "=l"(d) : "l"(a), "l"(b))
#define UNPACK2(lo, hi, p) \
    asm("mov.b64 {%0, %1}, %2;" : "=r"(lo), "=r"(hi) : "l"(p))

__device__ __forceinline__ uint32_t smem_u32(const void* p) {
    uint32_t a;
    asm("{ .reg .u64 t; cvta.to.shared.u64 t, %1; cvt.u32.u64 %0, t; }"
        : "=r"(a) : "l"(p));
    return a;
}
__device__ __forceinline__ void cp16(uint32_t dst, const void* src) {
    asm volatile("cp.async.cg.shared.global [%0], [%1], 16;"
                 :: "r"(dst), "l"(src) : "memory");
}
__device__ __forceinline__ void cp4(uint32_t dst, const void* src) {
    asm volatile("cp.async.ca.shared.global [%0], [%1], 4;"
                 :: "r"(dst), "l"(src) : "memory");
}
#define CP_COMMIT() asm volatile("cp.async.commit_group;" ::: "memory")
#define CP_WAIT1()  asm volatile("cp.async.wait_group 1;" ::: "memory")

// fp16 m16n8k16, f32 accumulate
__device__ __forceinline__ void mma_f16(float* c, const uint32_t* a,
                                        uint32_t b0, uint32_t b1) {
    asm volatile(
        "mma.sync.aligned.m16n8k16.row.col.f32.f16.f16.f32 "
        "{%0,%1,%2,%3}, {%4,%5,%6,%7}, {%8,%9}, {%0,%1,%2,%3};"
        : "+f"(c[0]), "+f"(c[1]), "+f"(c[2]), "+f"(c[3])
        : "r"(a[0]), "r"(a[1]), "r"(a[2]), "r"(a[3]), "r"(b0), "r"(b1));
}

// 2-term fp16 split: t=0 -> h1 = rn(x); t=1 -> h2 = rn(x - h1)
__device__ __forceinline__ __half split_term(float x, int t) {
    __half h1 = __float2half_rn(x);
    if (t == 0) return h1;
    return __float2half_rn(x - __half2float(h1));
}
__device__ __forceinline__ uint32_t pack2(__half a, __half b) {
    return (uint32_t)__half_as_ushort(a) | ((uint32_t)__half_as_ushort(b) << 16);
}

// ===========================================================================
// K0: transpose latents [B][D][S] -> g_latT[(b*S+s)][d]   (R1-identical)
// ===========================================================================
__global__ void k_transpose(const float* __restrict__ lat) {
    __shared__ float t[32][33];
    int b = blockIdx.z, d0 = blockIdx.y * 32, s0 = blockIdx.x * 32;
    int tx = threadIdx.x, ty = threadIdx.y;
#pragma unroll
    for (int j = 0; j < 32; j += 8)
        t[ty + j][tx] = lat[((b * DD) + (d0 + ty + j)) * SS + s0 + tx];
    __syncthreads();
#pragma unroll
    for (int j = 0; j < 32; j += 8)
        g_latT[(b * SS + s0 + ty + j) * DD + d0 + tx] = t[tx][ty + j];
}

// ===========================================================================
// K0b: codebook norms (R1-identical)
// ===========================================================================
__global__ void k_cbn(const float* __restrict__ cb) {
    int k = blockIdx.x * 256 + threadIdx.x;
    const float4* r = (const float4*)(cb + (size_t)k * DD);
    float a0 = 0.f, a1 = 0.f, a2 = 0.f, a3 = 0.f;
#pragma unroll
    for (int i = 0; i < 16; i++) {
        float4 v = r[i];
        a0 = fmaf(v.x, v.x, a0);
        a1 = fmaf(v.y, v.y, a1);
        a2 = fmaf(v.z, v.z, a2);
        a3 = fmaf(v.w, v.w, a3);
    }
    g_cbn[k] = (a0 + a1) + (a2 + a3);
}

// ===========================================================================
// K0c: row norms (bit-identical to R1's order)
// ===========================================================================
__global__ void k_rn() {
    int n = blockIdx.x * 256 + threadIdx.x;
    unsigned long long la[32];
    const ulonglong2* lp = (const ulonglong2*)(g_latT + (size_t)n * DD);
#pragma unroll
    for (int i = 0; i < 16; i++) {
        ulonglong2 v = lp[i];
        la[2 * i] = v.x;
        la[2 * i + 1] = v.y;
    }
    unsigned long long r0 = 0ull, r1 = 0ull, r2 = 0ull, r3 = 0ull;
#pragma unroll
    for (int i = 0; i < 32; i += 4) {
        FMA2(r0, la[i],     la[i],     r0);
        FMA2(r1, la[i + 1], la[i + 1], r1);
        FMA2(r2, la[i + 2], la[i + 2], r2);
        FMA2(r3, la[i + 3], la[i + 3], r3);
    }
    unsigned long long s0, s1, s;
    ADD2(s0, r0, r1); ADD2(s1, r2, r3); ADD2(s, s0, s1);
    unsigned lo, hi; UNPACK2(lo, hi, s);
    g_rn[n] = __uint_as_float(lo) + __uint_as_float(hi);
}

// ===========================================================================
// K0d: build fp16 A fragments (m16n8k16 layout).
// Blocks (wm:4)(s:4)(term:2)(i:2) x 32 lanes x 16B. Per-wm stride 8192 B.
// Lane l of block: row r = base + (l>>2), k0 = s*16 + (l&3)*2.
// uint4 = {a0,a1,a2,a3} = {(r,k0),(r,k0+1)},{(r+8,k0),...},{(r,k0+8),...},{(r+8,k0+8),...}
// ===========================================================================
__global__ void k_afrag() {
    int gid = blockIdx.x * 256 + threadIdx.x;    // 262144 uint4
    int cta = gid >> 11;
    int rem = gid & 2047;
    int wm = rem >> 9;
    int s = (rem >> 7) & 3;
    int t = (rem >> 6) & 1;
    int i = (rem >> 5) & 1;
    int lane = rem & 31;
    int r0 = cta * MTILE + wm * 32 + i * 16 + (lane >> 2);
    int k0 = s * 16 + (lane & 3) * 2;
    uint4 o;
    uint32_t* po = &o.x;
#pragma unroll
    for (int q = 0; q < 4; q++) {
        int dr = (q & 1) * 8;
        int dk = (q >> 1) * 8;
        float x0 = g_latT[(size_t)(r0 + dr) * DD + k0 + dk];
        float x1 = g_latT[(size_t)(r0 + dr) * DD + k0 + dk + 1];
        po[q] = pack2(split_term(x0, t), split_term(x1, t));
    }
    g_latfrag[gid] = o;
}

// ===========================================================================
// K0e: build fp16 B fragments, codebook pre-scaled by 2^13 (exact).
// Blocks (wn:2)(s:4)(term:2)(p:4) x 32 lanes x 16B. Per-wn stride 16384 B.
// uint4 = {j0.b0, j0.b1, j1.b0, j1.b1}, j0=2p, j1=2p+1;
// bX lane l: col c = wn*64 + j*8 + (l>>2); b0 rows k0,k0+1; b1 rows k0+8,k0+9.
// ===========================================================================
__global__ void k_bfrag(const float* __restrict__ cb) {
    int gid = blockIdx.x * 256 + threadIdx.x;    // 131072 uint4
    int tile = gid >> 11;
    int rem = gid & 2047;
    int wn = rem >> 10;
    int s = (rem >> 8) & 3;
    int t = (rem >> 7) & 1;
    int p = (rem >> 5) & 3;
    int lane = rem & 31;
    int g = lane >> 2;
    int k0 = s * 16 + (lane & 3) * 2;
    uint4 o;
    uint32_t* po = &o.x;
#pragma unroll
    for (int c = 0; c < 4; c++) {
        int j = 2 * p + (c >> 1);
        int dk = ((c & 1) ? 8 : 0);
        int code = tile * NT + wn * 64 + j * 8 + g;
        float x0 = cb[(size_t)code * DD + k0 + dk] * 8192.0f;   // exact
        float x1 = cb[(size_t)code * DD + k0 + dk + 1] * 8192.0f;
        po[c] = pack2(split_term(x0, t), split_term(x1, t));
    }
    g_cbfrag[gid] = o;
}

// ===========================================================================
// K1: fp16 m16n8k16 GEMM (3-pass split) + fused argmin. 128 CTAs x 256 thr.
// ===========================================================================
__global__ void __launch_bounds__(256, 1) k_gemm_argmin() {
    extern __shared__ char sm[];
    uint32_t sbase = smem_u32(sm);
    int tid = threadIdx.x;
    int lane = tid & 31;
    int wid = tid >> 5;
    int wm = wid >> 1;               // rows wm*32..+32
    int wn = wid & 1;                // cols wn*64..+64
    int cta = blockIdx.x;

    // ---- prologue prefetch: A (g0), B0+CN0 (g1), B1+CN1 (g2) ----
    {
        const char* asrc = (const char*)g_latfrag + (size_t)cta * A_BYTES;
#pragma unroll
        for (int c = 0; c < 8; c++)
            cp16(sbase + SM_A + (c * 256 + tid) * 16, asrc + (c * 256 + tid) * 16);
        CP_COMMIT();
        const char* bsrc = (const char*)g_cbfrag;
#pragma unroll
        for (int c = 0; c < 8; c++)
            cp16(sbase + SM_B0 + (c * 256 + tid) * 16, bsrc + (c * 256 + tid) * 16);
        if (tid < 128) cp4(sbase + SM_CN0 + tid * 4, g_cbn + tid);
        CP_COMMIT();
#pragma unroll
        for (int c = 0; c < 8; c++)
            cp16(sbase + SM_B1 + (c * 256 + tid) * 16,
                 bsrc + B_BYTES + (c * 256 + tid) * 16);
        if (tid < 128) cp4(sbase + SM_CN1 + tid * 4, g_cbn + 128 + tid);
        CP_COMMIT();
    }

    // per-thread rows: slot(i,h) -> cta*128 + wm*32 + i*16 + (lane>>2) + h*8
    float rn[4];
#pragma unroll
    for (int i = 0; i < 2; i++)
#pragma unroll
        for (int h = 0; h < 2; h++)
            rn[i * 2 + h] =
                g_rn[cta * MTILE + wm * 32 + i * 16 + (lane >> 2) + h * 8];

    float bestv[4] = {3.4e38f, 3.4e38f, 3.4e38f, 3.4e38f};
    int   besti[4] = {0, 0, 0, 0};

    uint32_t a_base = sbase + SM_A + (uint32_t)wm * 8192 + lane * 16;
    uint32_t cn_off = (uint32_t)(wn * 64 + (lane & 3) * 2) * 4;

    for (int t = 0; t < NITER; t++) {
        CP_WAIT1();
        __syncthreads();
        uint32_t b_base = sbase + ((t & 1) ? SM_B1 : SM_B0)
                          + (uint32_t)wn * 16384 + lane * 16;
        uint32_t cn_base = sbase + ((t & 1) ? SM_CN1 : SM_CN0) + cn_off;

        float acc[2][8][4];
#pragma unroll
        for (int i = 0; i < 2; i++)
#pragma unroll
            for (int j = 0; j < 8; j++)
#pragma unroll
                for (int v = 0; v < 4; v++) acc[i][j][v] = 0.f;

        // passes (ta,tb): (0,0), (1,0), (0,1)
#pragma unroll
        for (int pass = 0; pass < 3; pass++) {
            int ta = (pass == 1);
            int tb = (pass == 2);
#pragma unroll
            for (int s = 0; s < 4; s++) {
                uint32_t af[2][4];
#pragma unroll
                for (int i = 0; i < 2; i++) {
                    asm volatile("ld.shared.v4.b32 {%0,%1,%2,%3}, [%4];"
                        : "=r"(af[i][0]), "=r"(af[i][1]),
                          "=r"(af[i][2]), "=r"(af[i][3])
                        : "r"(a_base + (uint32_t)((s * 2 + ta) * 2 + i) * 512u));
                }
#pragma unroll
                for (int p = 0; p < 4; p++) {
                    uint32_t w0, w1, w2, w3;
                    asm volatile("ld.shared.v4.b32 {%0,%1,%2,%3}, [%4];"
                        : "=r"(w0), "=r"(w1), "=r"(w2), "=r"(w3)
                        : "r"(b_base + (uint32_t)((s * 2 + tb) * 4 + p) * 512u));
#pragma unroll
                    for (int i = 0; i < 2; i++) {
                        mma_f16(acc[i][2 * p],     af[i], w0, w1);
                        mma_f16(acc[i][2 * p + 1], af[i], w2, w3);
                    }
                }
            }
        }

        // fused argmin epilogue (ascending code index, strict <)
        // dist = (rn + cn) - 2*dot, dot = acc * 2^-13 -> fmaf(-2^-12, acc, rn+cn)
        int kb = t * NT + wn * 64 + 2 * (lane & 3);
#pragma unroll
        for (int j = 0; j < 8; j++) {
            float2 cn2;
            asm volatile("ld.shared.v2.b32 {%0,%1}, [%2];"
                : "=f"(cn2.x), "=f"(cn2.y) : "r"(cn_base + j * 32u));
#pragma unroll
            for (int i = 0; i < 2; i++) {
#pragma unroll
                for (int v = 0; v < 4; v++) {
                    float cn = (v & 1) ? cn2.y : cn2.x;
                    int slot = i * 2 + (v >> 1);
                    float dist = fmaf(DIST_SCALE, acc[i][j][v], rn[slot] + cn);
                    int idx = kb + j * 8 + (v & 1);
                    if (dist < bestv[slot]) { bestv[slot] = dist; besti[slot] = idx; }
                }
            }
        }
        __syncthreads();

        // prefetch tile t+2 into the buffer just consumed
        if (t + 2 < NITER) {
            const char* bsrc = (const char*)g_cbfrag + (size_t)(t + 2) * B_BYTES;
            uint32_t dst = sbase + ((t & 1) ? SM_B1 : SM_B0);
#pragma unroll
            for (int c = 0; c < 8; c++)
                cp16(dst + (c * 256 + tid) * 16, bsrc + (c * 256 + tid) * 16);
            if (tid < 128)
                cp4(sbase + ((t & 1) ? SM_CN1 : SM_CN0) + tid * 4,
                    g_cbn + (t + 2) * NT + tid);
        }
        CP_COMMIT();   // unconditional: keeps wait_group(1) accounting correct
    }

    // ---- final cross-thread argmin via u64 keys (dist>0 -> bits ordered) ----
    __syncthreads();
    unsigned long long* red = (unsigned long long*)sm;   // reuse A region, 8KB
    int slotcol = wn * 4 + (lane & 3);
#pragma unroll
    for (int i = 0; i < 2; i++)
#pragma unroll
        for (int h = 0; h < 2; h++) {
            int row = wm * 32 + i * 16 + (lane >> 2) + h * 8;
            unsigned long long key =
                ((unsigned long long)__float_as_uint(bestv[i * 2 + h]) << 32)
                | (unsigned)besti[i * 2 + h];
            red[row * 8 + slotcol] = key;
        }
    __syncthreads();
    if (tid < 128) {
        unsigned long long k = red[tid * 8];
#pragma unroll
        for (int c = 1; c < 8; c++) {
            unsigned long long v = red[tid * 8 + c];
            if (v < k) k = v;
        }
        g_idx[cta * MTILE + tid] = (int)(unsigned)k;
    }
}

// ===========================================================================
// K3: output gather (native layout, coalesced) + block loss partials (R1)
// ===========================================================================
__global__ void k_outloss(const float* __restrict__ lat,
                          const float* __restrict__ cb,
                          float* __restrict__ out) {
    int e = blockIdx.x * 256 + threadIdx.x;
    int s = e & (SS - 1);
    int bd = e >> 12;
    int d = bd & (DD - 1);
    int b = bd >> 6;
    int n = b * SS + s;
    int idx = g_idx[n];
    float q = cb[(size_t)idx * DD + d];
    float l = lat[e];
    out[e] = q;
    float df = q - l;
    float v = df * df;
#pragma unroll
    for (int o = 16; o > 0; o >>= 1) v += __shfl_down_sync(0xffffffffu, v, o);
    __shared__ float red[8];
    int w = threadIdx.x >> 5, ln = threadIdx.x & 31;
    if (ln == 0) red[w] = v;
    __syncthreads();
    if (threadIdx.x < 32) {
        float x = (threadIdx.x < 8) ? red[threadIdx.x] : 0.f;
#pragma unroll
        for (int o = 4; o > 0; o >>= 1) x += __shfl_down_sync(0xffffffffu, x, o);
        if (threadIdx.x == 0) g_losspart[blockIdx.x] = x;
    }
}

// ===========================================================================
// K4: final fixed-order reduce (R1)
// ===========================================================================
__global__ void k_final(const float* __restrict__ vqw,
                        float* __restrict__ out, int out_size) {
    __shared__ float sm2[256];
    int tid = threadIdx.x;
    float a = 0.f;
#pragma unroll
    for (int i = 0; i < 16; i++) a += g_losspart[tid * 16 + i];
    sm2[tid] = a;
    __syncthreads();
    for (int o = 128; o > 0; o >>= 1) {
        if (tid < o) sm2[tid] += sm2[tid + o];
        __syncthreads();
    }
    if (tid == 0 && out_size > OUT_TENSOR_ELEMS) {
        float w = vqw[0];
        out[out_size - 1] = sm2[0] * (1.f + w) * (1.f / (float)OUT_TENSOR_ELEMS);
    }
}

// ===========================================================================
extern "C" void kernel_launch(void* const* d_in, const int* in_sizes, int n_in,
                              void* d_out, int out_size) {
    const float* lat = (const float*)d_in[0];
    const float* vqw = (const float*)d_in[1];
    const float* cb  = (const float*)d_in[2];
    float* out = (float*)d_out;

    static int s_attr = 0;
    if (!s_attr) {
        cudaFuncSetAttribute(k_gemm_argmin,
                             cudaFuncAttributeMaxDynamicSharedMemorySize,
                             DSMEM_BYTES);
        s_attr = 1;
    }

    k_transpose<<<dim3(SS / 32, DD / 32, BB), dim3(32, 8)>>>(lat);
    k_cbn<<<KCODES / 256, 256>>>(cb);
    k_rn<<<NROWS / 256, 256>>>();
    k_afrag<<<1024, 256>>>();
    k_bfrag<<<512, 256>>>(cb);
    k_gemm_argmin<<<NROWS / MTILE, 256, DSMEM_BYTES>>>();
    k_outloss<<<OUT_TENSOR_ELEMS / 256, 256>>>(lat, cb, out);
    k_final<<<1, 256>>>(vqw, out, out_size);
}

// round 7
// speedup vs baseline: 3.5390x; 1.1270x over previous
#include <cuda_runtime.h>
#include <cuda_fp16.h>
#include <cstdint>

// ===========================================================================
// Problem constants
// ===========================================================================
#define NROWS 16384          // B*X*Y*Z latent rows
#define DD    64
#define KCODES 8192
#define SS    4096           // X*Y*Z
#define BB    4
#define OUT_TENSOR_ELEMS (NROWS*DD)

#define MTILE 128            // rows per CTA
#define NT    128            // codes per iteration tile
#define NITER (KCODES/NT)    // 64
#define A_BYTES 32768        // 128 rows x 64 k x 2 terms x 2B (fp16 fragment order)
#define B_BYTES 32768        // 128 codes x 64 k x 2 terms x 2B

// B pre-scaled by 2^13 (exact). Epilogue rescale: -2*dot = -acc * 2^-12.
#define DIST_SCALE (-0.000244140625f)   /* -2^-12 */

// dynamic smem (gemm): A 32K | B x3 32K | CN x3 512B
#define SM_A   0
#define SM_B(s)  (32768 + (s) * 32768)
#define SM_CN(s) (131072 + (s) * 512)
#define DSMEM_BYTES 132608

// ===========================================================================
// Device scratch (allocation-free rule)
// ===========================================================================
__device__ float g_rn[NROWS];
__device__ float g_cbn[KCODES];
__device__ uint4 g_latfrag[(NROWS / MTILE) * (A_BYTES / 16)];  // 4 MB
__device__ uint4 g_cbfrag[NITER * (B_BYTES / 16)];             // 2 MB
__device__ int   g_idx[NROWS];
__device__ float g_losspart[4096];

// ===========================================================================
// Helpers
// ===========================================================================
__device__ __forceinline__ uint32_t smem_u32(const void* p) {
    uint32_t a;
    asm("{ .reg .u64 t; cvta.to.shared.u64 t, %1; cvt.u32.u64 %0, t; }"
        : "=r"(a) : "l"(p));
    return a;
}
__device__ __forceinline__ void cp16(uint32_t dst, const void* src) {
    asm volatile("cp.async.cg.shared.global [%0], [%1], 16;"
                 :: "r"(dst), "l"(src) : "memory");
}
__device__ __forceinline__ void cp4(uint32_t dst, const void* src) {
    asm volatile("cp.async.ca.shared.global [%0], [%1], 4;"
                 :: "r"(dst), "l"(src) : "memory");
}
#define CP_COMMIT() asm volatile("cp.async.commit_group;" ::: "memory")
#define CP_WAIT1()  asm volatile("cp.async.wait_group 1;" ::: "memory")
#define CP_WAIT2()  asm volatile("cp.async.wait_group 2;" ::: "memory")

// fp16 m16n8k16, f32 accumulate
__device__ __forceinline__ void mma_f16(float* c, const uint32_t* a,
                                        uint32_t b0, uint32_t b1) {
    asm volatile(
        "mma.sync.aligned.m16n8k16.row.col.f32.f16.f16.f32 "
        "{%0,%1,%2,%3}, {%4,%5,%6,%7}, {%8,%9}, {%0,%1,%2,%3};"
        : "+f"(c[0]), "+f"(c[1]), "+f"(c[2]), "+f"(c[3])
        : "r"(a[0]), "r"(a[1]), "r"(a[2]), "r"(a[3]), "r"(b0), "r"(b1));
}

// 2-term fp16 split: t=0 -> h1 = rn(x); t=1 -> h2 = rn(x - h1)
__device__ __forceinline__ __half split_term(float x, int t) {
    __half h1 = __float2half_rn(x);
    if (t == 0) return h1;
    return __float2half_rn(x - __half2float(h1));
}
__device__ __forceinline__ uint32_t pack2(__half a, __half b) {
    return (uint32_t)__half_as_ushort(a) | ((uint32_t)__half_as_ushort(b) << 16);
}

// ===========================================================================
// K_prepA: fused transpose + row norms + A-fragment build.
// Grid 128 CTAs (one per 128-row block), 256 threads.
// rn arithmetic replicates R1's packed-f32x2 op sequence exactly.
// ===========================================================================
__global__ void k_prepA(const float* __restrict__ lat) {
    __shared__ float lt[128][65];
    int cta = blockIdx.x;
    int tid = threadIdx.x;
    int b = cta >> 5;                 // 32 row-blocks per batch (4096/128)
    int s0 = (cta & 31) * 128;

    // transpose-load: thread t handles dim d = t>>2, s-chunk (t&3)*32
    {
        int d = tid >> 2;
        int sc = (tid & 3) * 32;
        const float4* src =
            (const float4*)(lat + ((size_t)b * DD + d) * SS + s0 + sc);
#pragma unroll
        for (int i = 0; i < 8; i++) {
            float4 v = src[i];
            lt[sc + 4 * i + 0][d] = v.x;
            lt[sc + 4 * i + 1][d] = v.y;
            lt[sc + 4 * i + 2][d] = v.z;
            lt[sc + 4 * i + 3][d] = v.w;
        }
    }
    __syncthreads();

    // row norm, replicating R1's packed accumulation order bit-for-bit:
    // r_j(lo) over dims 8m+2j, r_j(hi) over dims 8m+2j+1 (m ascending);
    // slo=(r0+r1)+(r2+r3) per lane; rn = slo+shi.
    if (tid < 128) {
        float rl[4] = {0.f, 0.f, 0.f, 0.f};
        float rh[4] = {0.f, 0.f, 0.f, 0.f};
#pragma unroll
        for (int m = 0; m < 8; m++) {
#pragma unroll
            for (int j = 0; j < 4; j++) {
                float xl = lt[tid][8 * m + 2 * j];
                float xh = lt[tid][8 * m + 2 * j + 1];
                rl[j] = fmaf(xl, xl, rl[j]);
                rh[j] = fmaf(xh, xh, rh[j]);
            }
        }
        float slo = (rl[0] + rl[1]) + (rl[2] + rl[3]);
        float shi = (rh[0] + rh[1]) + (rh[2] + rh[3]);
        g_rn[cta * MTILE + tid] = slo + shi;
    }

    // A fragments: 2048 uint4 per CTA, 8 per thread.
    // Blocks (wm:4)(s:4)(term:2)(i:2) x 32 lanes.
#pragma unroll
    for (int f8 = 0; f8 < 8; f8++) {
        int f = f8 * 256 + tid;
        int wm = f >> 9;
        int s = (f >> 7) & 3;
        int term = (f >> 6) & 1;
        int ii = (f >> 5) & 1;
        int lane = f & 31;
        int r0 = wm * 32 + ii * 16 + (lane >> 2);
        int k0 = s * 16 + (lane & 3) * 2;
        uint4 o;
        uint32_t* po = &o.x;
#pragma unroll
        for (int q = 0; q < 4; q++) {
            int dr = (q & 1) * 8;
            int dk = (q >> 1) * 8;
            float x0 = lt[r0 + dr][k0 + dk];
            float x1 = lt[r0 + dr][k0 + dk + 1];
            po[q] = pack2(split_term(x0, term), split_term(x1, term));
        }
        g_latfrag[cta * 2048 + f] = o;
    }
}

// ===========================================================================
// K_prepB: fused codebook norms + B-fragment build (scaled by 2^13, exact).
// Grid 64 CTAs (one per 128-code tile), 256 threads.
// cbn arithmetic replicates R1's float4 accumulation order exactly.
// ===========================================================================
__global__ void k_prepB(const float* __restrict__ cb) {
    __shared__ float cbs[128][65];
    int tile = blockIdx.x;
    int tid = threadIdx.x;
    int kc0 = tile * NT;

    {
        int code = tid >> 1;
        int half = tid & 1;
        const float4* src =
            (const float4*)(cb + (size_t)(kc0 + code) * DD) + half * 8;
#pragma unroll
        for (int i = 0; i < 8; i++) {
            float4 v = src[i];
            cbs[code][half * 32 + 4 * i + 0] = v.x;
            cbs[code][half * 32 + 4 * i + 1] = v.y;
            cbs[code][half * 32 + 4 * i + 2] = v.z;
            cbs[code][half * 32 + 4 * i + 3] = v.w;
        }
    }
    __syncthreads();

    if (tid < 128) {
        float a[4] = {0.f, 0.f, 0.f, 0.f};
#pragma unroll
        for (int i = 0; i < 16; i++) {
#pragma unroll
            for (int j = 0; j < 4; j++) {
                float v = cbs[tid][4 * i + j];
                a[j] = fmaf(v, v, a[j]);
            }
        }
        g_cbn[kc0 + tid] = (a[0] + a[1]) + (a[2] + a[3]);
    }

    // B fragments: 2048 uint4 per tile, 8 per thread.
    // Blocks (wn:2)(s:4)(term:2)(p:4) x 32 lanes.
#pragma unroll
    for (int f8 = 0; f8 < 8; f8++) {
        int f = f8 * 256 + tid;
        int wn = f >> 10;
        int s = (f >> 8) & 3;
        int term = (f >> 7) & 1;
        int p = (f >> 5) & 3;
        int lane = f & 31;
        int g = lane >> 2;
        int k0 = s * 16 + (lane & 3) * 2;
        uint4 o;
        uint32_t* po = &o.x;
#pragma unroll
        for (int c = 0; c < 4; c++) {
            int j = 2 * p + (c >> 1);
            int dk = ((c & 1) ? 8 : 0);
            int code = wn * 64 + j * 8 + g;
            float x0 = cbs[code][k0 + dk] * 8192.0f;      // exact scale
            float x1 = cbs[code][k0 + dk + 1] * 8192.0f;
            po[c] = pack2(split_term(x0, term), split_term(x1, term));
        }
        g_cbfrag[tile * 2048 + f] = o;
    }
}

// ===========================================================================
// K1: fp16 m16n8k16 GEMM (3-pass split) + fused argmin.
// 128 CTAs x 256 thr. A fragments register-resident; 3-stage cp.async pipe,
// one __syncthreads per iteration; B loads shared between passes 0/1.
// ===========================================================================
__global__ void __launch_bounds__(256, 1) k_gemm_argmin() {
    extern __shared__ char sm[];
    uint32_t sbase = smem_u32(sm);
    int tid = threadIdx.x;
    int lane = tid & 31;
    int wid = tid >> 5;
    int wm = wid >> 1;               // rows wm*32..+32
    int wn = wid & 1;                // cols wn*64..+64
    int cta = blockIdx.x;

    // ---- prologue: A (g0), B tile0+CN0 (g1), B tile1+CN1 (g2) ----
    {
        const char* asrc = (const char*)g_latfrag + (size_t)cta * A_BYTES;
#pragma unroll
        for (int c = 0; c < 8; c++)
            cp16(sbase + SM_A + (c * 256 + tid) * 16, asrc + (c * 256 + tid) * 16);
        CP_COMMIT();
        const char* bsrc = (const char*)g_cbfrag;
#pragma unroll
        for (int c = 0; c < 8; c++)
            cp16(sbase + SM_B(0) + (c * 256 + tid) * 16, bsrc + (c * 256 + tid) * 16);
        if (tid < 128) cp4(sbase + SM_CN(0) + tid * 4, g_cbn + tid);
        CP_COMMIT();
#pragma unroll
        for (int c = 0; c < 8; c++)
            cp16(sbase + SM_B(1) + (c * 256 + tid) * 16,
                 bsrc + B_BYTES + (c * 256 + tid) * 16);
        if (tid < 128) cp4(sbase + SM_CN(1) + tid * 4, g_cbn + 128 + tid);
        CP_COMMIT();
    }

    // per-thread rows: slot(i,h) -> cta*128 + wm*32 + i*16 + (lane>>2) + h*8
    float rn[4];
#pragma unroll
    for (int i = 0; i < 2; i++)
#pragma unroll
        for (int h = 0; h < 2; h++)
            rn[i * 2 + h] =
                g_rn[cta * MTILE + wm * 32 + i * 16 + (lane >> 2) + h * 8];

    // ---- wait for A, cache all 16 A fragments in registers ----
    CP_WAIT2();
    __syncthreads();
    uint32_t af[2][4][2][4];         // [term][s][i][4regs]
    {
        uint32_t a_base = sbase + SM_A + (uint32_t)wm * 8192 + lane * 16;
#pragma unroll
        for (int term = 0; term < 2; term++)
#pragma unroll
            for (int s = 0; s < 4; s++)
#pragma unroll
                for (int i = 0; i < 2; i++) {
                    asm volatile("ld.shared.v4.b32 {%0,%1,%2,%3}, [%4];"
                        : "=r"(af[term][s][i][0]), "=r"(af[term][s][i][1]),
                          "=r"(af[term][s][i][2]), "=r"(af[term][s][i][3])
                        : "r"(a_base +
                              (uint32_t)((s * 2 + term) * 2 + i) * 512u));
                }
    }

    float bestv[4] = {3.4e38f, 3.4e38f, 3.4e38f, 3.4e38f};
    int   besti[4] = {0, 0, 0, 0};
    uint32_t cn_off = (uint32_t)(wn * 64 + (lane & 3) * 2) * 4;

    int sel = 0;
    for (int t = 0; t < NITER; t++) {
        CP_WAIT1();
        __syncthreads();

        // prefetch tile t+2 into slot (sel+2)%3 (consumed at t-1) — safe
        // because cp.async is issued after the barrier above.
        int psel = sel + 2; if (psel >= 3) psel -= 3;
        if (t + 2 < NITER) {
            const char* bsrc = (const char*)g_cbfrag + (size_t)(t + 2) * B_BYTES;
            uint32_t dst = sbase + SM_B(psel);
#pragma unroll
            for (int c = 0; c < 8; c++)
                cp16(dst + (c * 256 + tid) * 16, bsrc + (c * 256 + tid) * 16);
            if (tid < 128)
                cp4(sbase + SM_CN(psel) + tid * 4, g_cbn + (t + 2) * NT + tid);
        }
        CP_COMMIT();   // unconditional: keeps wait_group accounting uniform

        uint32_t b_base = sbase + SM_B(sel) + (uint32_t)wn * 16384 + lane * 16;
        uint32_t cn_base = sbase + SM_CN(sel) + cn_off;

        float acc[2][8][4];
#pragma unroll
        for (int i = 0; i < 2; i++)
#pragma unroll
            for (int j = 0; j < 8; j++)
#pragma unroll
                for (int v = 0; v < 4; v++) acc[i][j][v] = 0.f;

        // tb=0: used by A terms 0 and 1 (one B load feeds 8 MMAs)
#pragma unroll
        for (int s = 0; s < 4; s++) {
#pragma unroll
            for (int p = 0; p < 4; p++) {
                uint32_t w0, w1, w2, w3;
                asm volatile("ld.shared.v4.b32 {%0,%1,%2,%3}, [%4];"
                    : "=r"(w0), "=r"(w1), "=r"(w2), "=r"(w3)
                    : "r"(b_base + (uint32_t)((s * 2 + 0) * 4 + p) * 512u));
#pragma unroll
                for (int at = 0; at < 2; at++)
#pragma unroll
                    for (int i = 0; i < 2; i++) {
                        mma_f16(acc[i][2 * p],     af[at][s][i], w0, w1);
                        mma_f16(acc[i][2 * p + 1], af[at][s][i], w2, w3);
                    }
            }
        }
        // tb=1: used by A term 0 only
#pragma unroll
        for (int s = 0; s < 4; s++) {
#pragma unroll
            for (int p = 0; p < 4; p++) {
                uint32_t w0, w1, w2, w3;
                asm volatile("ld.shared.v4.b32 {%0,%1,%2,%3}, [%4];"
                    : "=r"(w0), "=r"(w1), "=r"(w2), "=r"(w3)
                    : "r"(b_base + (uint32_t)((s * 2 + 1) * 4 + p) * 512u));
#pragma unroll
                for (int i = 0; i < 2; i++) {
                    mma_f16(acc[i][2 * p],     af[0][s][i], w0, w1);
                    mma_f16(acc[i][2 * p + 1], af[0][s][i], w2, w3);
                }
            }
        }

        // fused argmin epilogue (ascending code index, strict <)
        // dist = (rn + cn) - 2*dot = fmaf(-2^-12, acc, rn+cn)
        int kb = t * NT + wn * 64 + 2 * (lane & 3);
#pragma unroll
        for (int j = 0; j < 8; j++) {
            float2 cn2;
            asm volatile("ld.shared.v2.b32 {%0,%1}, [%2];"
                : "=f"(cn2.x), "=f"(cn2.y) : "r"(cn_base + j * 32u));
#pragma unroll
            for (int i = 0; i < 2; i++) {
#pragma unroll
                for (int v = 0; v < 4; v++) {
                    float cn = (v & 1) ? cn2.y : cn2.x;
                    int slot = i * 2 + (v >> 1);
                    float dist = fmaf(DIST_SCALE, acc[i][j][v], rn[slot] + cn);
                    int idx = kb + j * 8 + (v & 1);
                    if (dist < bestv[slot]) { bestv[slot] = dist; besti[slot] = idx; }
                }
            }
        }

        sel++; if (sel >= 3) sel -= 3;
    }

    // ---- final cross-thread argmin via u64 keys (dist>0 -> bits ordered) ----
    __syncthreads();
    unsigned long long* red = (unsigned long long*)sm;   // reuse A region, 8KB
    int slotcol = wn * 4 + (lane & 3);
#pragma unroll
    for (int i = 0; i < 2; i++)
#pragma unroll
        for (int h = 0; h < 2; h++) {
            int row = wm * 32 + i * 16 + (lane >> 2) + h * 8;
            unsigned long long key =
                ((unsigned long long)__float_as_uint(bestv[i * 2 + h]) << 32)
                | (unsigned)besti[i * 2 + h];
            red[row * 8 + slotcol] = key;
        }
    __syncthreads();
    if (tid < 128) {
        unsigned long long k = red[tid * 8];
#pragma unroll
        for (int c = 1; c < 8; c++) {
            unsigned long long v = red[tid * 8 + c];
            if (v < k) k = v;
        }
        g_idx[cta * MTILE + tid] = (int)(unsigned)k;
    }
}

// ===========================================================================
// K3: output gather (native layout, coalesced) + block loss partials (R1)
// ===========================================================================
__global__ void k_outloss(const float* __restrict__ lat,
                          const float* __restrict__ cb,
                          float* __restrict__ out) {
    int e = blockIdx.x * 256 + threadIdx.x;
    int s = e & (SS - 1);
    int bd = e >> 12;
    int d = bd & (DD - 1);
    int b = bd >> 6;
    int n = b * SS + s;
    int idx = g_idx[n];
    float q = cb[(size_t)idx * DD + d];
    float l = lat[e];
    out[e] = q;
    float df = q - l;
    float v = df * df;
#pragma unroll
    for (int o = 16; o > 0; o >>= 1) v += __shfl_down_sync(0xffffffffu, v, o);
    __shared__ float red[8];
    int w = threadIdx.x >> 5, ln = threadIdx.x & 31;
    if (ln == 0) red[w] = v;
    __syncthreads();
    if (threadIdx.x < 32) {
        float x = (threadIdx.x < 8) ? red[threadIdx.x] : 0.f;
#pragma unroll
        for (int o = 4; o > 0; o >>= 1) x += __shfl_down_sync(0xffffffffu, x, o);
        if (threadIdx.x == 0) g_losspart[blockIdx.x] = x;
    }
}

// ===========================================================================
// K4: final fixed-order reduce (R1)
// ===========================================================================
__global__ void k_final(const float* __restrict__ vqw,
                        float* __restrict__ out, int out_size) {
    __shared__ float sm2[256];
    int tid = threadIdx.x;
    float a = 0.f;
#pragma unroll
    for (int i = 0; i < 16; i++) a += g_losspart[tid * 16 + i];
    sm2[tid] = a;
    __syncthreads();
    for (int o = 128; o > 0; o >>= 1) {
        if (tid < o) sm2[tid] += sm2[tid + o];
        __syncthreads();
    }
    if (tid == 0 && out_size > OUT_TENSOR_ELEMS) {
        float w = vqw[0];
        out[out_size - 1] = sm2[0] * (1.f + w) * (1.f / (float)OUT_TENSOR_ELEMS);
    }
}

// ===========================================================================
extern "C" void kernel_launch(void* const* d_in, const int* in_sizes, int n_in,
                              void* d_out, int out_size) {
    const float* lat = (const float*)d_in[0];
    const float* vqw = (const float*)d_in[1];
    const float* cb  = (const float*)d_in[2];
    float* out = (float*)d_out;

    static int s_attr = 0;
    if (!s_attr) {
        cudaFuncSetAttribute(k_gemm_argmin,
                             cudaFuncAttributeMaxDynamicSharedMemorySize,
                             DSMEM_BYTES);
        s_attr = 1;
    }

    k_prepA<<<NROWS / MTILE, 256>>>(lat);
    k_prepB<<<NITER, 256>>>(cb);
    k_gemm_argmin<<<NROWS / MTILE, 256, DSMEM_BYTES>>>();
    k_outloss<<<OUT_TENSOR_ELEMS / 256, 256>>>(lat, cb, out);
    k_final<<<1, 256>>>(vqw, out, out_size);
}

// round 8
// speedup vs baseline: 3.6314x; 1.0261x over previous
#include <cuda_runtime.h>
#include <cuda_fp16.h>
#include <cstdint>

// ===========================================================================
// Problem constants
// ===========================================================================
#define NROWS 16384          // B*X*Y*Z latent rows
#define DD    64
#define KCODES 8192
#define SS    4096           // X*Y*Z
#define BB    4
#define OUT_TENSOR_ELEMS (NROWS*DD)

#define MTILE 128            // rows per CTA
#define NT    128            // codes per iteration tile
#define NITER (KCODES/NT)    // 64
#define A_BYTES 32768        // 128 rows x 64 k x 2 terms x 2B (fp16 fragment order)
#define B_BYTES 32768        // 128 codes x 64 k x 2 terms x 2B

// B pre-scaled by 2^13 (exact). Epilogue rescale: -2*dot = -acc * 2^-12.
#define DIST_SCALE (-0.000244140625f)   /* -2^-12 */

// dynamic smem (gemm): A 32K | B x3 32K | CN x3 512B
#define SM_A   0
#define SM_B(s)  (32768 + (s) * 32768)
#define SM_CN(s) (131072 + (s) * 512)
#define DSMEM_BYTES 132608

// ===========================================================================
// Device scratch (allocation-free rule)
// ===========================================================================
__device__ float g_rn[NROWS];
__device__ float g_cbn[KCODES];
__device__ uint4 g_latfrag[(NROWS / MTILE) * (A_BYTES / 16)];  // 4 MB
__device__ uint4 g_cbfrag[NITER * (B_BYTES / 16)];             // 2 MB
__device__ int   g_idx[NROWS];
__device__ float g_losspart[4096];

// ===========================================================================
// Helpers
// ===========================================================================
__device__ __forceinline__ uint32_t smem_u32(const void* p) {
    uint32_t a;
    asm("{ .reg .u64 t; cvta.to.shared.u64 t, %1; cvt.u32.u64 %0, t; }"
        : "=r"(a) : "l"(p));
    return a;
}
__device__ __forceinline__ void cp16(uint32_t dst, const void* src) {
    asm volatile("cp.async.cg.shared.global [%0], [%1], 16;"
                 :: "r"(dst), "l"(src) : "memory");
}
__device__ __forceinline__ void cp4(uint32_t dst, const void* src) {
    asm volatile("cp.async.ca.shared.global [%0], [%1], 4;"
                 :: "r"(dst), "l"(src) : "memory");
}
#define CP_COMMIT() asm volatile("cp.async.commit_group;" ::: "memory")
#define CP_WAIT1()  asm volatile("cp.async.wait_group 1;" ::: "memory")
#define CP_WAIT2()  asm volatile("cp.async.wait_group 2;" ::: "memory")

// fp16 m16n8k16, f32 accumulate
__device__ __forceinline__ void mma_f16(float* c, const uint32_t* a,
                                        uint32_t b0, uint32_t b1) {
    asm volatile(
        "mma.sync.aligned.m16n8k16.row.col.f32.f16.f16.f32 "
        "{%0,%1,%2,%3}, {%4,%5,%6,%7}, {%8,%9}, {%0,%1,%2,%3};"
        : "+f"(c[0]), "+f"(c[1]), "+f"(c[2]), "+f"(c[3])
        : "r"(a[0]), "r"(a[1]), "r"(a[2]), "r"(a[3]), "r"(b0), "r"(b1));
}

// 2-term fp16 split: t=0 -> h1 = rn(x); t=1 -> h2 = rn(x - h1)
__device__ __forceinline__ __half split_term(float x, int t) {
    __half h1 = __float2half_rn(x);
    if (t == 0) return h1;
    return __float2half_rn(x - __half2float(h1));
}
__device__ __forceinline__ uint32_t pack2(__half a, __half b) {
    return (uint32_t)__half_as_ushort(a) | ((uint32_t)__half_as_ushort(b) << 16);
}

// ===========================================================================
// K_prep: merged prepA (CTAs 0..127) + prepB (CTAs 128..191).
// prepA: transpose + row norms + A fragments (rn order replicates R1).
// prepB: codebook norms + B fragments, scaled by 2^13 (cbn order = R1).
// ===========================================================================
__global__ void k_prep(const float* __restrict__ lat,
                       const float* __restrict__ cb) {
    __shared__ float ts[128][65];
    int tid = threadIdx.x;

    if (blockIdx.x < 128) {
        int cta = blockIdx.x;
        int b = cta >> 5;                 // 32 row-blocks per batch
        int s0 = (cta & 31) * 128;

        // transpose-load: thread t -> dim d = t>>2, s-chunk (t&3)*32
        {
            int d = tid >> 2;
            int sc = (tid & 3) * 32;
            const float4* src =
                (const float4*)(lat + ((size_t)b * DD + d) * SS + s0 + sc);
#pragma unroll
            for (int i = 0; i < 8; i++) {
                float4 v = src[i];
                ts[sc + 4 * i + 0][d] = v.x;
                ts[sc + 4 * i + 1][d] = v.y;
                ts[sc + 4 * i + 2][d] = v.z;
                ts[sc + 4 * i + 3][d] = v.w;
            }
        }
        __syncthreads();

        // row norm, replicating R1's packed accumulation order bit-for-bit
        if (tid < 128) {
            float rl[4] = {0.f, 0.f, 0.f, 0.f};
            float rh[4] = {0.f, 0.f, 0.f, 0.f};
#pragma unroll
            for (int m = 0; m < 8; m++) {
#pragma unroll
                for (int j = 0; j < 4; j++) {
                    float xl = ts[tid][8 * m + 2 * j];
                    float xh = ts[tid][8 * m + 2 * j + 1];
                    rl[j] = fmaf(xl, xl, rl[j]);
                    rh[j] = fmaf(xh, xh, rh[j]);
                }
            }
            float slo = (rl[0] + rl[1]) + (rl[2] + rl[3]);
            float shi = (rh[0] + rh[1]) + (rh[2] + rh[3]);
            g_rn[cta * MTILE + tid] = slo + shi;
        }

        // A fragments: blocks (wm:4)(s:4)(term:2)(i:2) x 32 lanes
#pragma unroll
        for (int f8 = 0; f8 < 8; f8++) {
            int f = f8 * 256 + tid;
            int wm = f >> 9;
            int s = (f >> 7) & 3;
            int term = (f >> 6) & 1;
            int ii = (f >> 5) & 1;
            int lane = f & 31;
            int r0 = wm * 32 + ii * 16 + (lane >> 2);
            int k0 = s * 16 + (lane & 3) * 2;
            uint4 o;
            uint32_t* po = &o.x;
#pragma unroll
            for (int q = 0; q < 4; q++) {
                int dr = (q & 1) * 8;
                int dk = (q >> 1) * 8;
                float x0 = ts[r0 + dr][k0 + dk];
                float x1 = ts[r0 + dr][k0 + dk + 1];
                po[q] = pack2(split_term(x0, term), split_term(x1, term));
            }
            g_latfrag[cta * 2048 + f] = o;
        }
    } else {
        int tile = blockIdx.x - 128;
        int kc0 = tile * NT;

        {
            int code = tid >> 1;
            int half = tid & 1;
            const float4* src =
                (const float4*)(cb + (size_t)(kc0 + code) * DD) + half * 8;
#pragma unroll
            for (int i = 0; i < 8; i++) {
                float4 v = src[i];
                ts[code][half * 32 + 4 * i + 0] = v.x;
                ts[code][half * 32 + 4 * i + 1] = v.y;
                ts[code][half * 32 + 4 * i + 2] = v.z;
                ts[code][half * 32 + 4 * i + 3] = v.w;
            }
        }
        __syncthreads();

        if (tid < 128) {
            float a[4] = {0.f, 0.f, 0.f, 0.f};
#pragma unroll
            for (int i = 0; i < 16; i++) {
#pragma unroll
                for (int j = 0; j < 4; j++) {
                    float v = ts[tid][4 * i + j];
                    a[j] = fmaf(v, v, a[j]);
                }
            }
            g_cbn[kc0 + tid] = (a[0] + a[1]) + (a[2] + a[3]);
        }

        // B fragments: blocks (wn:2)(s:4)(term:2)(p:4) x 32 lanes
#pragma unroll
        for (int f8 = 0; f8 < 8; f8++) {
            int f = f8 * 256 + tid;
            int wn = f >> 10;
            int s = (f >> 8) & 3;
            int term = (f >> 7) & 1;
            int p = (f >> 5) & 3;
            int lane = f & 31;
            int g = lane >> 2;
            int k0 = s * 16 + (lane & 3) * 2;
            uint4 o;
            uint32_t* po = &o.x;
#pragma unroll
            for (int c = 0; c < 4; c++) {
                int j = 2 * p + (c >> 1);
                int dk = ((c & 1) ? 8 : 0);
                int code = wn * 64 + j * 8 + g;
                float x0 = ts[code][k0 + dk] * 8192.0f;      // exact scale
                float x1 = ts[code][k0 + dk + 1] * 8192.0f;
                po[c] = pack2(split_term(x0, term), split_term(x1, term));
            }
            g_cbfrag[tile * 2048 + f] = o;
        }
    }
}

// ===========================================================================
// K1: fp16 m16n8k16 GEMM (3-pass split) + fused argmin.
// MMA stream rescheduled for accumulator-reuse distance 16 (was 4):
// per s-step, B fragments for a whole tb row are register-cached and the
// at=0 / at=1 / tb=1 blocks each touch all 16 accumulators once.
// ===========================================================================
__global__ void __launch_bounds__(256, 1) k_gemm_argmin() {
    extern __shared__ char sm[];
    uint32_t sbase = smem_u32(sm);
    int tid = threadIdx.x;
    int lane = tid & 31;
    int wid = tid >> 5;
    int wm = wid >> 1;               // rows wm*32..+32
    int wn = wid & 1;                // cols wn*64..+64
    int cta = blockIdx.x;

    // ---- prologue: A (g0), B tile0+CN0 (g1), B tile1+CN1 (g2) ----
    {
        const char* asrc = (const char*)g_latfrag + (size_t)cta * A_BYTES;
#pragma unroll
        for (int c = 0; c < 8; c++)
            cp16(sbase + SM_A + (c * 256 + tid) * 16, asrc + (c * 256 + tid) * 16);
        CP_COMMIT();
        const char* bsrc = (const char*)g_cbfrag;
#pragma unroll
        for (int c = 0; c < 8; c++)
            cp16(sbase + SM_B(0) + (c * 256 + tid) * 16, bsrc + (c * 256 + tid) * 16);
        if (tid < 128) cp4(sbase + SM_CN(0) + tid * 4, g_cbn + tid);
        CP_COMMIT();
#pragma unroll
        for (int c = 0; c < 8; c++)
            cp16(sbase + SM_B(1) + (c * 256 + tid) * 16,
                 bsrc + B_BYTES + (c * 256 + tid) * 16);
        if (tid < 128) cp4(sbase + SM_CN(1) + tid * 4, g_cbn + 128 + tid);
        CP_COMMIT();
    }

    // per-thread rows: slot(i,h) -> cta*128 + wm*32 + i*16 + (lane>>2) + h*8
    float rn[4];
#pragma unroll
    for (int i = 0; i < 2; i++)
#pragma unroll
        for (int h = 0; h < 2; h++)
            rn[i * 2 + h] =
                g_rn[cta * MTILE + wm * 32 + i * 16 + (lane >> 2) + h * 8];

    // ---- wait for A, cache all 16 A fragments in registers ----
    CP_WAIT2();
    __syncthreads();
    uint32_t af[2][4][2][4];         // [term][s][i][4regs]
    {
        uint32_t a_base = sbase + SM_A + (uint32_t)wm * 8192 + lane * 16;
#pragma unroll
        for (int term = 0; term < 2; term++)
#pragma unroll
            for (int s = 0; s < 4; s++)
#pragma unroll
                for (int i = 0; i < 2; i++) {
                    asm volatile("ld.shared.v4.b32 {%0,%1,%2,%3}, [%4];"
                        : "=r"(af[term][s][i][0]), "=r"(af[term][s][i][1]),
                          "=r"(af[term][s][i][2]), "=r"(af[term][s][i][3])
                        : "r"(a_base +
                              (uint32_t)((s * 2 + term) * 2 + i) * 512u));
                }
    }

    float bestv[4] = {3.4e38f, 3.4e38f, 3.4e38f, 3.4e38f};
    int   besti[4] = {0, 0, 0, 0};
    uint32_t cn_off = (uint32_t)(wn * 64 + (lane & 3) * 2) * 4;

    int sel = 0;
    for (int t = 0; t < NITER; t++) {
        CP_WAIT1();
        __syncthreads();

        // prefetch tile t+2 into slot (sel+2)%3 (consumed at t-1)
        int psel = sel + 2; if (psel >= 3) psel -= 3;
        if (t + 2 < NITER) {
            const char* bsrc = (const char*)g_cbfrag + (size_t)(t + 2) * B_BYTES;
            uint32_t dst = sbase + SM_B(psel);
#pragma unroll
            for (int c = 0; c < 8; c++)
                cp16(dst + (c * 256 + tid) * 16, bsrc + (c * 256 + tid) * 16);
            if (tid < 128)
                cp4(sbase + SM_CN(psel) + tid * 4, g_cbn + (t + 2) * NT + tid);
        }
        CP_COMMIT();   // unconditional: keeps wait_group accounting uniform

        uint32_t b_base = sbase + SM_B(sel) + (uint32_t)wn * 16384 + lane * 16;
        uint32_t cn_base = sbase + SM_CN(sel) + cn_off;

        float acc[2][8][4];
#pragma unroll
        for (int i = 0; i < 2; i++)
#pragma unroll
            for (int j = 0; j < 8; j++)
#pragma unroll
                for (int v = 0; v < 4; v++) acc[i][j][v] = 0.f;

#pragma unroll
        for (int s = 0; s < 4; s++) {
            uint32_t bw[4][4];
            // B fragments for tb=0 row of this s (shared by at=0 and at=1)
#pragma unroll
            for (int p = 0; p < 4; p++)
                asm volatile("ld.shared.v4.b32 {%0,%1,%2,%3}, [%4];"
                    : "=r"(bw[p][0]), "=r"(bw[p][1]),
                      "=r"(bw[p][2]), "=r"(bw[p][3])
                    : "r"(b_base + (uint32_t)((s * 2 + 0) * 4 + p) * 512u));
            // at=0: 16 MMAs, 16 distinct accumulators
#pragma unroll
            for (int p = 0; p < 4; p++) {
                mma_f16(acc[0][2 * p],     af[0][s][0], bw[p][0], bw[p][1]);
                mma_f16(acc[0][2 * p + 1], af[0][s][0], bw[p][2], bw[p][3]);
                mma_f16(acc[1][2 * p],     af[0][s][1], bw[p][0], bw[p][1]);
                mma_f16(acc[1][2 * p + 1], af[0][s][1], bw[p][2], bw[p][3]);
            }
            // at=1: same 16 accumulators, reuse distance 16
#pragma unroll
            for (int p = 0; p < 4; p++) {
                mma_f16(acc[0][2 * p],     af[1][s][0], bw[p][0], bw[p][1]);
                mma_f16(acc[0][2 * p + 1], af[1][s][0], bw[p][2], bw[p][3]);
                mma_f16(acc[1][2 * p],     af[1][s][1], bw[p][0], bw[p][1]);
                mma_f16(acc[1][2 * p + 1], af[1][s][1], bw[p][2], bw[p][3]);
            }
            // tb=1 row, A term 0: another 16, distance 16
#pragma unroll
            for (int p = 0; p < 4; p++)
                asm volatile("ld.shared.v4.b32 {%0,%1,%2,%3}, [%4];"
                    : "=r"(bw[p][0]), "=r"(bw[p][1]),
                      "=r"(bw[p][2]), "=r"(bw[p][3])
                    : "r"(b_base + (uint32_t)((s * 2 + 1) * 4 + p) * 512u));
#pragma unroll
            for (int p = 0; p < 4; p++) {
                mma_f16(acc[0][2 * p],     af[0][s][0], bw[p][0], bw[p][1]);
                mma_f16(acc[0][2 * p + 1], af[0][s][0], bw[p][2], bw[p][3]);
                mma_f16(acc[1][2 * p],     af[0][s][1], bw[p][0], bw[p][1]);
                mma_f16(acc[1][2 * p + 1], af[0][s][1], bw[p][2], bw[p][3]);
            }
        }

        // fused argmin epilogue (ascending code index, strict <)
        // dist = (rn + cn) - 2*dot = fmaf(-2^-12, acc, rn+cn)
        int kb = t * NT + wn * 64 + 2 * (lane & 3);
#pragma unroll
        for (int j = 0; j < 8; j++) {
            float2 cn2;
            asm volatile("ld.shared.v2.b32 {%0,%1}, [%2];"
                : "=f"(cn2.x), "=f"(cn2.y) : "r"(cn_base + j * 32u));
#pragma unroll
            for (int i = 0; i < 2; i++) {
#pragma unroll
                for (int v = 0; v < 4; v++) {
                    float cn = (v & 1) ? cn2.y : cn2.x;
                    int slot = i * 2 + (v >> 1);
                    float dist = fmaf(DIST_SCALE, acc[i][j][v], rn[slot] + cn);
                    int idx = kb + j * 8 + (v & 1);
                    if (dist < bestv[slot]) { bestv[slot] = dist; besti[slot] = idx; }
                }
            }
        }

        sel++; if (sel >= 3) sel -= 3;
    }

    // ---- final cross-thread argmin via u64 keys (dist>0 -> bits ordered) ----
    __syncthreads();
    unsigned long long* red = (unsigned long long*)sm;   // reuse A region, 8KB
    int slotcol = wn * 4 + (lane & 3);
#pragma unroll
    for (int i = 0; i < 2; i++)
#pragma unroll
        for (int h = 0; h < 2; h++) {
            int row = wm * 32 + i * 16 + (lane >> 2) + h * 8;
            unsigned long long key =
                ((unsigned long long)__float_as_uint(bestv[i * 2 + h]) << 32)
                | (unsigned)besti[i * 2 + h];
            red[row * 8 + slotcol] = key;
        }
    __syncthreads();
    if (tid < 128) {
        unsigned long long k = red[tid * 8];
#pragma unroll
        for (int c = 1; c < 8; c++) {
            unsigned long long v = red[tid * 8 + c];
            if (v < k) k = v;
        }
        g_idx[cta * MTILE + tid] = (int)(unsigned)k;
    }
}

// ===========================================================================
// K3: output gather (native layout, coalesced) + block loss partials (R1)
// ===========================================================================
__global__ void k_outloss(const float* __restrict__ lat,
                          const float* __restrict__ cb,
                          float* __restrict__ out) {
    int e = blockIdx.x * 256 + threadIdx.x;
    int s = e & (SS - 1);
    int bd = e >> 12;
    int d = bd & (DD - 1);
    int b = bd >> 6;
    int n = b * SS + s;
    int idx = g_idx[n];
    float q = cb[(size_t)idx * DD + d];
    float l = lat[e];
    out[e] = q;
    float df = q - l;
    float v = df * df;
#pragma unroll
    for (int o = 16; o > 0; o >>= 1) v += __shfl_down_sync(0xffffffffu, v, o);
    __shared__ float red[8];
    int w = threadIdx.x >> 5, ln = threadIdx.x & 31;
    if (ln == 0) red[w] = v;
    __syncthreads();
    if (threadIdx.x < 32) {
        float x = (threadIdx.x < 8) ? red[threadIdx.x] : 0.f;
#pragma unroll
        for (int o = 4; o > 0; o >>= 1) x += __shfl_down_sync(0xffffffffu, x, o);
        if (threadIdx.x == 0) g_losspart[blockIdx.x] = x;
    }
}

// ===========================================================================
// K4: final fixed-order reduce (R1)
// ===========================================================================
__global__ void k_final(const float* __restrict__ vqw,
                        float* __restrict__ out, int out_size) {
    __shared__ float sm2[256];
    int tid = threadIdx.x;
    float a = 0.f;
#pragma unroll
    for (int i = 0; i < 16; i++) a += g_losspart[tid * 16 + i];
    sm2[tid] = a;
    __syncthreads();
    for (int o = 128; o > 0; o >>= 1) {
        if (tid < o) sm2[tid] += sm2[tid + o];
        __syncthreads();
    }
    if (tid == 0 && out_size > OUT_TENSOR_ELEMS) {
        float w = vqw[0];
        out[out_size - 1] = sm2[0] * (1.f + w) * (1.f / (float)OUT_TENSOR_ELEMS);
    }
}

// ===========================================================================
extern "C" void kernel_launch(void* const* d_in, const int* in_sizes, int n_in,
                              void* d_out, int out_size) {
    const float* lat = (const float*)d_in[0];
    const float* vqw = (const float*)d_in[1];
    const float* cb  = (const float*)d_in[2];
    float* out = (float*)d_out;

    static int s_attr = 0;
    if (!s_attr) {
        cudaFuncSetAttribute(k_gemm_argmin,
                             cudaFuncAttributeMaxDynamicSharedMemorySize,
                             DSMEM_BYTES);
        s_attr = 1;
    }

    k_prep<<<192, 256>>>(lat, cb);
    k_gemm_argmin<<<NROWS / MTILE, 256, DSMEM_BYTES>>>();
    k_outloss<<<OUT_TENSOR_ELEMS / 256, 256>>>(lat, cb, out);
    k_final<<<1, 256>>>(vqw, out, out_size);
}